// round 2
// baseline (speedup 1.0000x reference)
#include <cuda_runtime.h>

typedef unsigned long long u64;

// ---- packed f32x2 helpers (Blackwell packed FP32; ptxas never auto-fuses) ----
__device__ __forceinline__ u64 pack2(float lo, float hi) {
    u64 r; asm("mov.b64 %0, {%1, %2};" : "=l"(r) : "f"(lo), "f"(hi)); return r;
}
__device__ __forceinline__ void unpack2(u64 v, float& lo, float& hi) {
    asm("mov.b64 {%0, %1}, %2;" : "=f"(lo), "=f"(hi) : "l"(v));
}
__device__ __forceinline__ u64 fma2(u64 a, u64 b, u64 c) {
    u64 d; asm("fma.rn.f32x2 %0, %1, %2, %3;" : "=l"(d) : "l"(a), "l"(b), "l"(c)); return d;
}

// ---- accurate fast transcendentals (MUFU EX2 ~2^-22 rel err, RCP ~1 ulp) ----
__device__ __forceinline__ float ex2f(float x) { float r; asm("ex2.approx.f32 %0, %1;" : "=f"(r) : "f"(x)); return r; }
__device__ __forceinline__ float rcpf(float x) { float r; asm("rcp.approx.f32 %0, %1;" : "=f"(r) : "f"(x)); return r; }
__device__ __forceinline__ float sigf(float x)   { return rcpf(1.0f + ex2f(-1.4426950408889634f * x)); }
__device__ __forceinline__ float tanhf_(float x) { return fmaf(-2.0f, rcpf(1.0f + ex2f(2.8853900817779268f * x)), 1.0f); }

#define TSTEPS 512
#define WARPS_PER_CTA 4
#define ROWS_PER_WARP 2

// One warp processes TWO batch rows (shared W_hh registers, 4 independent fma2
// chains). Lane j owns hidden unit j. Gates packed (i,f) / (g,o) as f32x2.
// h broadcast via ping-pong SMEM buffer -> ONE __syncwarp per timestep.
__global__ void __launch_bounds__(32 * WARPS_PER_CTA, 3)
lstm_kernel(const float* __restrict__ x,
            const float* __restrict__ W_ih,
            const float* __restrict__ W_hh,
            const float* __restrict__ b_ih,
            const float* __restrict__ b_hh,
            const float* __restrict__ W_fc,
            const float* __restrict__ b_fc,
            float* __restrict__ out, int B)
{
    // ping-pong per-warp h buffers: [phase][warp][row*32 + k], value = {h,h}
    __shared__ u64 hbuf[2][WARPS_PER_CTA][64];
    __shared__ u64 s_bias01[32], s_bias23[32];

    const int wl   = threadIdx.x >> 5;
    const int lane = threadIdx.x & 31;
    const int wg   = blockIdx.x * WARPS_PER_CTA + wl;
    const int bA   = wg * ROWS_PER_WARP;
    const int bB   = bA + 1;

    if (threadIdx.x < 32) {
        s_bias01[lane] = pack2(b_ih[lane]      + b_hh[lane],
                               b_ih[32 + lane] + b_hh[32 + lane]);
        s_bias23[lane] = pack2(b_ih[64 + lane] + b_hh[64 + lane],
                               b_ih[96 + lane] + b_hh[96 + lane]);
    }

    // ---- preload W_hh into registers: 128 regs/lane, shared by both rows ----
    u64 w01[32], w23[32];
#pragma unroll
    for (int k = 0; k < 32; k++) {
        w01[k] = pack2(W_hh[(lane)      * 32 + k], W_hh[(32 + lane) * 32 + k]);
        w23[k] = pack2(W_hh[(64 + lane) * 32 + k], W_hh[(96 + lane) * 32 + k]);
    }
    const u64 wih01 = pack2(W_ih[lane],      W_ih[32 + lane]);
    const u64 wih23 = pack2(W_ih[64 + lane], W_ih[96 + lane]);

    float hA = 0.f, cA = 0.f, hB = 0.f, cB = 0.f;
    hbuf[0][wl][lane]      = 0ull;
    hbuf[0][wl][32 + lane] = 0ull;
    __syncthreads();   // bias table + h init visible

    if (bA >= B) return;

    const float* xA = x + (size_t)bA * TSTEPS;
    const float* xB = x + (size_t)bB * TSTEPS;

    int p = 0;
#pragma unroll 1
    for (int tc = 0; tc < TSTEPS; tc += 32) {
        float xcA = xA[tc + lane];   // coalesced 128B per warp per 32 steps
        float xcB = xB[tc + lane];
#pragma unroll 1
        for (int tt = 0; tt < 32; tt++) {
            const float xvA = __shfl_sync(0xffffffffu, xcA, tt);
            const float xvB = __shfl_sync(0xffffffffu, xcB, tt);
            const u64 bias01 = s_bias01[lane];
            const u64 bias23 = s_bias23[lane];
            u64 aA01 = fma2(pack2(xvA, xvA), wih01, bias01);
            u64 aA23 = fma2(pack2(xvA, xvA), wih23, bias23);
            u64 aB01 = fma2(pack2(xvB, xvB), wih01, bias01);
            u64 aB23 = fma2(pack2(xvB, xvB), wih23, bias23);

            const u64* hp = hbuf[p][wl];
#pragma unroll
            for (int k = 0; k < 32; k++) {
                const u64 hkA = hp[k];        // broadcast LDS.64 {hA[k],hA[k]}
                const u64 hkB = hp[32 + k];   // broadcast LDS.64 {hB[k],hB[k]}
                aA01 = fma2(w01[k], hkA, aA01);
                aA23 = fma2(w23[k], hkA, aA23);
                aB01 = fma2(w01[k], hkB, aB01);
                aB23 = fma2(w23[k], hkB, aB23);
            }

            // ---- row A tail ----
            float ai, af, ag, ao;
            unpack2(aA01, ai, af);
            unpack2(aA23, ag, ao);
            float igA = sigf(ai), fgA = sigf(af), ggA = tanhf_(ag), ogA = sigf(ao);
            cA = fmaf(fgA, cA, igA * ggA);
            hA = ogA * tanhf_(cA);
            // ---- row B tail (independent: overlaps A's MUFU latency) ----
            float bi, bf, bg, bo;
            unpack2(aB01, bi, bf);
            unpack2(aB23, bg, bo);
            float igB = sigf(bi), fgB = sigf(bf), ggB = tanhf_(bg), ogB = sigf(bo);
            cB = fmaf(fgB, cB, igB * ggB);
            hB = ogB * tanhf_(cB);

            u64* hq = hbuf[p ^ 1][wl];
            hq[lane]      = pack2(hA, hA);
            hq[32 + lane] = pack2(hB, hB);
            __syncwarp();    // single barrier: orders this write for next step's
                             // reads AND next step's writes vs this step's reads
            p ^= 1;
        }
    }

    // ---- final head: out[b] = dot(h, W_fc) + b_fc (both rows) ----
    const float wfc = W_fc[lane];
    float pA = hA * wfc, pB = hB * wfc;
#pragma unroll
    for (int off = 16; off; off >>= 1) {
        pA += __shfl_xor_sync(0xffffffffu, pA, off);
        pB += __shfl_xor_sync(0xffffffffu, pB, off);
    }
    if (lane == 0) {
        out[bA] = pA + b_fc[0];
        if (bB < B) out[bB] = pB + b_fc[0];
    }
}

extern "C" void kernel_launch(void* const* d_in, const int* in_sizes, int n_in,
                              void* d_out, int out_size)
{
    const float* x    = (const float*)d_in[0];
    const float* W_ih = (const float*)d_in[1];
    const float* W_hh = (const float*)d_in[2];
    const float* b_ih = (const float*)d_in[3];
    const float* b_hh = (const float*)d_in[4];
    const float* W_fc = (const float*)d_in[5];
    const float* b_fc = (const float*)d_in[6];
    float* out = (float*)d_out;

    int B = in_sizes[0] / TSTEPS;  // x is [B, 512, 1]
    int rows_per_cta = WARPS_PER_CTA * ROWS_PER_WARP;
    int blocks = (B + rows_per_cta - 1) / rows_per_cta;
    lstm_kernel<<<blocks, 32 * WARPS_PER_CTA>>>(x, W_ih, W_hh, b_ih, b_hh, W_fc, b_fc, out, B);
}